// round 1
// baseline (speedup 1.0000x reference)
#include <cuda_runtime.h>
#include <cuda_bf16.h>
#include <cstddef>

#define BB 8
#define CC 512
#define NHEADS 8
#define HD 64
#define NN 1024
#define NGROUPS 32
#define GSIZE ((CC / NGROUPS) * NN)   // 16 * 1024 = 16384
#define EPSV 1e-5f

// ---------------- scratch (static device globals; no runtime alloc) ----------------
__device__ float g_xn[BB * CC * NN];                          // 16 MB
__device__ float g_qkv[BB * 3 * CC * NN];                     // 48 MB
__device__ float g_scores[(size_t)BB * NHEADS * NN * NN];     // 256 MB
__device__ float g_ao[BB * CC * NN];                          // 16 MB

// ---------------- GroupNorm ----------------
// one block per (b, g); group = contiguous 16 channels * 1024 spatial
__global__ void groupnorm_kernel(const float* __restrict__ x,
                                 const float* __restrict__ w,
                                 const float* __restrict__ bch,
                                 float* __restrict__ xn) {
    int bg = blockIdx.x;
    const float* xp = x + (size_t)bg * GSIZE;
    float* op = xn + (size_t)bg * GSIZE;
    int t = threadIdx.x;

    float s = 0.f, s2 = 0.f;
    for (int i = t; i < GSIZE; i += blockDim.x) {
        float v = xp[i];
        s += v; s2 += v * v;
    }
    __shared__ float rs[32], rs2[32];
    for (int o = 16; o; o >>= 1) {
        s  += __shfl_xor_sync(0xffffffffu, s,  o);
        s2 += __shfl_xor_sync(0xffffffffu, s2, o);
    }
    if ((t & 31) == 0) { rs[t >> 5] = s; rs2[t >> 5] = s2; }
    __syncthreads();
    if (t < 32) {
        int nw = blockDim.x >> 5;
        float a  = (t < nw) ? rs[t]  : 0.f;
        float a2 = (t < nw) ? rs2[t] : 0.f;
        for (int o = 16; o; o >>= 1) {
            a  += __shfl_xor_sync(0xffffffffu, a,  o);
            a2 += __shfl_xor_sync(0xffffffffu, a2, o);
        }
        if (t == 0) {
            float mean = a / (float)GSIZE;
            float var  = a2 / (float)GSIZE - mean * mean;
            rs[0]  = mean;
            rs2[0] = rsqrtf(var + EPSV);
        }
    }
    __syncthreads();
    float mean = rs[0], rstd = rs2[0];
    int c0 = (bg % NGROUPS) * (CC / NGROUPS);
    for (int i = t; i < GSIZE; i += blockDim.x) {
        int c = c0 + i / NN;
        op[i] = (xp[i] - mean) * rstd * w[c] + bch[c];
    }
}

// ---------------- generic batched SGEMM ----------------
// C[M,N] = opA(A) * opB(B) (+ bias[row]) (+ residual)
// TA: A(i,k) = A[k*lda + i], else A[i*lda + k]
// TB: B(k,j) = B[j*ldb + k], else B[k*ldb + j]
// batch z = blockIdx.z decomposed as zo = z/hdiv, zi = z%hdiv; ptr += zo*sXo + zi*sXi
// tile: 64x64x16, 256 threads, 4x4 per-thread microtile. All dims assumed multiples.
template <bool TA, bool TB>
__global__ void gemm_kernel(const float* __restrict__ A,
                            const float* __restrict__ Bm,
                            float* __restrict__ Cm,
                            int M, int Nc, int K,
                            int lda, int ldb, int ldc,
                            long long sAo, long long sAi,
                            long long sBo, long long sBi,
                            long long sCo, long long sCi,
                            int hdiv,
                            const float* __restrict__ bias,
                            const float* __restrict__ res,
                            long long sRo, long long sRi) {
    int z = blockIdx.z;
    int zo = z / hdiv, zi = z % hdiv;
    A  += zo * sAo + zi * sAi;
    Bm += zo * sBo + zi * sBi;
    Cm += zo * sCo + zi * sCi;
    if (res) res += zo * sRo + zi * sRi;

    __shared__ float As[16][68];
    __shared__ float Bs[16][68];

    int t = threadIdx.x;
    int tx = t & 15, ty = t >> 4;
    int i0 = blockIdx.x * 64, j0 = blockIdx.y * 64;

    float acc[4][4] = {};

    for (int k0 = 0; k0 < K; k0 += 16) {
#pragma unroll
        for (int r = 0; r < 4; r++) {
            int l = t + 256 * r;
            if (TA) {
                int k = l >> 6, i = l & 63;
                As[k][i] = A[(size_t)(k0 + k) * lda + (i0 + i)];
            } else {
                int i = l >> 4, k = l & 15;
                As[k][i] = A[(size_t)(i0 + i) * lda + (k0 + k)];
            }
        }
#pragma unroll
        for (int r = 0; r < 4; r++) {
            int l = t + 256 * r;
            if (TB) {
                int j = l >> 4, k = l & 15;
                Bs[k][j] = Bm[(size_t)(j0 + j) * ldb + (k0 + k)];
            } else {
                int k = l >> 6, j = l & 63;
                Bs[k][j] = Bm[(size_t)(k0 + k) * ldb + (j0 + j)];
            }
        }
        __syncthreads();
#pragma unroll
        for (int k = 0; k < 16; k++) {
            float4 ra = *(const float4*)&As[k][ty * 4];
            float4 rb = *(const float4*)&Bs[k][tx * 4];
            float a0 = ra.x, a1 = ra.y, a2 = ra.z, a3 = ra.w;
            float b0 = rb.x, b1 = rb.y, b2 = rb.z, b3 = rb.w;
            acc[0][0] += a0 * b0; acc[0][1] += a0 * b1; acc[0][2] += a0 * b2; acc[0][3] += a0 * b3;
            acc[1][0] += a1 * b0; acc[1][1] += a1 * b1; acc[1][2] += a1 * b2; acc[1][3] += a1 * b3;
            acc[2][0] += a2 * b0; acc[2][1] += a2 * b1; acc[2][2] += a2 * b2; acc[2][3] += a2 * b3;
            acc[3][0] += a3 * b0; acc[3][1] += a3 * b1; acc[3][2] += a3 * b2; acc[3][3] += a3 * b3;
        }
        __syncthreads();
    }

#pragma unroll
    for (int i = 0; i < 4; i++) {
        int gi = i0 + ty * 4 + i;
        float bv = bias ? bias[gi] : 0.f;
#pragma unroll
        for (int j = 0; j < 4; j++) {
            int gj = j0 + tx * 4 + j;
            float v = acc[i][j] + bv;
            if (res) v += res[(size_t)gi * ldc + gj];
            Cm[(size_t)gi * ldc + gj] = v;
        }
    }
}

// ---------------- row softmax (scale * S, then softmax over last dim) ----------------
// one 256-thread block per row of length 1024
__global__ void softmax_kernel(float* __restrict__ S) {
    float* p = S + (size_t)blockIdx.x * NN;
    int t = threadIdx.x;
    const float scale = 0.125f;   // 64^-0.5

    float v0 = p[t] * scale;
    float v1 = p[t + 256] * scale;
    float v2 = p[t + 512] * scale;
    float v3 = p[t + 768] * scale;

    __shared__ float red[32];
    float m = fmaxf(fmaxf(v0, v1), fmaxf(v2, v3));
    for (int o = 16; o; o >>= 1) m = fmaxf(m, __shfl_xor_sync(0xffffffffu, m, o));
    if ((t & 31) == 0) red[t >> 5] = m;
    __syncthreads();
    if (t < 32) {
        float x = (t < 8) ? red[t] : -1e30f;
        for (int o = 4; o; o >>= 1) x = fmaxf(x, __shfl_xor_sync(0xffffffffu, x, o));
        if (t == 0) red[0] = x;
    }
    __syncthreads();
    m = red[0];
    __syncthreads();

    v0 = __expf(v0 - m); v1 = __expf(v1 - m);
    v2 = __expf(v2 - m); v3 = __expf(v3 - m);
    float s = v0 + v1 + v2 + v3;
    for (int o = 16; o; o >>= 1) s += __shfl_xor_sync(0xffffffffu, s, o);
    if ((t & 31) == 0) red[t >> 5] = s;
    __syncthreads();
    if (t < 32) {
        float x = (t < 8) ? red[t] : 0.f;
        for (int o = 4; o; o >>= 1) x += __shfl_xor_sync(0xffffffffu, x, o);
        if (t == 0) red[0] = x;
    }
    __syncthreads();
    float inv = 1.0f / red[0];

    p[t]       = v0 * inv;
    p[t + 256] = v1 * inv;
    p[t + 512] = v2 * inv;
    p[t + 768] = v3 * inv;
}

// ---------------- launch ----------------
extern "C" void kernel_launch(void* const* d_in, const int* in_sizes, int n_in,
                              void* d_out, int out_size) {
    (void)in_sizes; (void)n_in; (void)out_size;
    const float* x  = (const float*)d_in[0];
    const float* nw = (const float*)d_in[1];
    const float* nb = (const float*)d_in[2];
    const float* qw = (const float*)d_in[3];
    const float* qb = (const float*)d_in[4];
    const float* pw = (const float*)d_in[5];
    const float* pb = (const float*)d_in[6];
    float* out = (float*)d_out;

    float *xn, *qkv, *sc, *ao;
    cudaGetSymbolAddress((void**)&xn,  g_xn);
    cudaGetSymbolAddress((void**)&qkv, g_qkv);
    cudaGetSymbolAddress((void**)&sc,  g_scores);
    cudaGetSymbolAddress((void**)&ao,  g_ao);

    const long long bCN   = (long long)CC * NN;          // 512*1024
    const long long b3CN  = 3LL * CC * NN;               // per-batch qkv stride
    const long long hN    = (long long)HD * NN;          // per-head stride
    const long long nnsq  = (long long)NN * NN;

    // 1) GroupNorm
    groupnorm_kernel<<<BB * NGROUPS, 256>>>(x, nw, nb, xn);

    // 2) QKV: per batch, qkv[b] = qkv_w [1536,512] * xn[b] [512,1024] + qkv_b
    gemm_kernel<false, false><<<dim3(24, 16, BB), 256>>>(
        qw, xn, qkv, 3 * CC, NN, CC, CC, NN, NN,
        0, 0, bCN, 0, b3CN, 0, 1, qb, nullptr, 0, 0);

    // 3) Scores: per (b,h), S = q^T [1024,64] * k [64,1024]
    gemm_kernel<true, false><<<dim3(16, 16, BB * NHEADS), 256>>>(
        qkv, qkv + (size_t)CC * NN, sc, NN, NN, HD, NN, NN, NN,
        b3CN, hN, b3CN, hN, (long long)NHEADS * nnsq, nnsq, NHEADS,
        nullptr, nullptr, 0, 0);

    // 4) Softmax over rows of S (with 1/8 scale)
    softmax_kernel<<<BB * NHEADS * NN, 256>>>(sc);

    // 5) AV: per (b,h), out[c,n] = v [64,1024] * P^T  (P row-major [n,m])
    gemm_kernel<false, true><<<dim3(1, 16, BB * NHEADS), 256>>>(
        qkv + 2 * (size_t)CC * NN, sc, ao, HD, NN, NN, NN, NN, NN,
        b3CN, hN, (long long)NHEADS * nnsq, nnsq, bCN, hN, NHEADS,
        nullptr, nullptr, 0, 0);

    // 6) Proj + bias + residual: out[b] = proj_w * ao[b] + proj_b + x[b]
    gemm_kernel<false, false><<<dim3(8, 16, BB), 256>>>(
        pw, ao, out, CC, NN, CC, CC, NN, NN,
        0, 0, bCN, 0, bCN, 0, 1, pb, x, bCN, 0);
}

// round 2
// speedup vs baseline: 2.0965x; 2.0965x over previous
#include <cuda_runtime.h>
#include <cuda_bf16.h>
#include <cstddef>

#define BB 8
#define CC 512
#define NHEADS 8
#define HD 64
#define NN 1024
#define NGROUPS 32
#define GSIZE ((CC / NGROUPS) * NN)   // 16384
#define EPSV 1e-5f

// ---------------- scratch ----------------
__device__ float g_xn[BB * CC * NN];                          // 16 MB
__device__ float g_qkv[BB * 3 * CC * NN];                     // 48 MB
__device__ float g_scores[(size_t)BB * NHEADS * NN * NN];     // 256 MB
__device__ float g_ao[BB * CC * NN];                          // 16 MB

// ---------------- GroupNorm ----------------
__global__ void groupnorm_kernel(const float* __restrict__ x,
                                 const float* __restrict__ w,
                                 const float* __restrict__ bch,
                                 float* __restrict__ xn) {
    int bg = blockIdx.x;
    const float* xp = x + (size_t)bg * GSIZE;
    float* op = xn + (size_t)bg * GSIZE;
    int t = threadIdx.x;

    float s = 0.f, s2 = 0.f;
    for (int i = t; i < GSIZE; i += blockDim.x) {
        float v = xp[i];
        s += v; s2 += v * v;
    }
    __shared__ float rs[32], rs2[32];
    for (int o = 16; o; o >>= 1) {
        s  += __shfl_xor_sync(0xffffffffu, s,  o);
        s2 += __shfl_xor_sync(0xffffffffu, s2, o);
    }
    if ((t & 31) == 0) { rs[t >> 5] = s; rs2[t >> 5] = s2; }
    __syncthreads();
    if (t < 32) {
        int nw = blockDim.x >> 5;
        float a  = (t < nw) ? rs[t]  : 0.f;
        float a2 = (t < nw) ? rs2[t] : 0.f;
        for (int o = 16; o; o >>= 1) {
            a  += __shfl_xor_sync(0xffffffffu, a,  o);
            a2 += __shfl_xor_sync(0xffffffffu, a2, o);
        }
        if (t == 0) {
            float mean = a / (float)GSIZE;
            float var  = a2 / (float)GSIZE - mean * mean;
            rs[0]  = mean;
            rs2[0] = rsqrtf(var + EPSV);
        }
    }
    __syncthreads();
    float mean = rs[0], rstd = rs2[0];
    int c0 = (bg % NGROUPS) * (CC / NGROUPS);
    for (int i = t; i < GSIZE; i += blockDim.x) {
        int c = c0 + i / NN;
        op[i] = (xp[i] - mean) * rstd * w[c] + bch[c];
    }
}

// ---------------- tf32 helpers ----------------
__device__ __forceinline__ unsigned f2tf32(float x) {
    unsigned r;
    asm("cvt.rna.tf32.f32 %0, %1;" : "=r"(r) : "f"(x));
    return r;
}

__device__ __forceinline__ void mma_tf32(float& c0, float& c1, float& c2, float& c3,
                                         unsigned a0, unsigned a1, unsigned a2, unsigned a3,
                                         unsigned b0, unsigned b1) {
    asm volatile(
        "mma.sync.aligned.m16n8k8.row.col.f32.tf32.tf32.f32 "
        "{%0,%1,%2,%3}, {%4,%5,%6,%7}, {%8,%9}, {%0,%1,%2,%3};\n"
        : "+f"(c0), "+f"(c1), "+f"(c2), "+f"(c3)
        : "r"(a0), "r"(a1), "r"(a2), "r"(a3), "r"(b0), "r"(b1));
}

// ---------------- tf32 tensor-core batched GEMM ----------------
// C[M,N] = opA(A) * opB(B) (+bias[row]) (+res), tile BMx128x32, 256 threads.
// TA: A(i,k)=A[k*lda+i] else A[i*lda+k];  TB: B(k,j)=B[j*ldb+k] else B[k*ldb+j]
#define BN 128
#define BK 32
#define LDA_S 36
#define LDB_S 132

template <int BM, bool TA, bool TB>
__global__ __launch_bounds__(256)
void mma_gemm(const float* __restrict__ A,
              const float* __restrict__ Bm,
              float* __restrict__ Cm,
              int K, int lda, int ldb, int ldc,
              long long sAo, long long sAi,
              long long sBo, long long sBi,
              long long sCo, long long sCi,
              int hdiv,
              const float* __restrict__ bias,
              const float* __restrict__ res,
              long long sRo, long long sRi) {
    int z = blockIdx.z;
    int zo = z / hdiv, zi = z % hdiv;
    A  += zo * sAo + zi * sAi;
    Bm += zo * sBo + zi * sBi;
    Cm += zo * sCo + zi * sCi;
    if (res) res += zo * sRo + zi * sRi;

    __shared__ unsigned As[BM * LDA_S];
    __shared__ unsigned Bs[BK * LDB_S];

    const int t  = threadIdx.x;
    const int w  = t >> 5, ln = t & 31;
    const int wr = w >> 2, wc = w & 3;        // 2 x 4 warp grid
    const int i0 = blockIdx.x * BM, j0 = blockIdx.y * BN;
    const int MF = BM / 32;                   // 16-row m-frags per warp

    float acc[MF][4][4];
#pragma unroll
    for (int a = 0; a < MF; a++)
#pragma unroll
        for (int b = 0; b < 4; b++)
#pragma unroll
            for (int c = 0; c < 4; c++) acc[a][b][c] = 0.f;

    for (int k0 = 0; k0 < K; k0 += BK) {
        // ---- load A tile -> As[i][k] ----
        if (TA) {
            // A(i,k) = A[k*lda + i]; scalar, coalesced along i
#pragma unroll
            for (int r = 0; r < BM * BK / 256; r++) {
                int idx = t + 256 * r;
                int i = idx % BM, k = idx / BM;
                As[i * LDA_S + k] = f2tf32(A[(size_t)(k0 + k) * lda + (i0 + i)]);
            }
        } else {
#pragma unroll
            for (int r = 0; r < BM * BK / 1024; r++) {
                int idx = t + 256 * r;
                int row = idx >> 3, kq = idx & 7;
                float4 v = *(const float4*)&A[(size_t)(i0 + row) * lda + k0 + kq * 4];
                uint4 u;
                u.x = f2tf32(v.x); u.y = f2tf32(v.y);
                u.z = f2tf32(v.z); u.w = f2tf32(v.w);
                *(uint4*)&As[row * LDA_S + kq * 4] = u;
            }
        }
        // ---- load B tile -> Bs[k][j] ----
        if (TB) {
            // B(k,j) = B[j*ldb + k]; scalar, coalesced along k
#pragma unroll
            for (int r = 0; r < BK * BN / 256; r++) {
                int idx = t + 256 * r;
                int k = idx & 31, j = idx >> 5;
                Bs[k * LDB_S + j] = f2tf32(Bm[(size_t)(j0 + j) * ldb + (k0 + k)]);
            }
        } else {
#pragma unroll
            for (int r = 0; r < BK * BN / 1024; r++) {
                int idx = t + 256 * r;
                int k = idx >> 5, jq = idx & 31;
                float4 v = *(const float4*)&Bm[(size_t)(k0 + k) * ldb + j0 + jq * 4];
                uint4 u;
                u.x = f2tf32(v.x); u.y = f2tf32(v.y);
                u.z = f2tf32(v.z); u.w = f2tf32(v.w);
                *(uint4*)&Bs[k * LDB_S + jq * 4] = u;
            }
        }
        __syncthreads();

        // ---- compute ----
#pragma unroll
        for (int ks = 0; ks < 4; ks++) {
            int kk = ks * 8;
            unsigned af[MF][4];
            unsigned bf[4][2];
#pragma unroll
            for (int mi = 0; mi < MF; mi++) {
                int mR = wr * (BM / 2) + mi * 16 + (ln >> 2);
                int ca = kk + (ln & 3);
                af[mi][0] = As[mR * LDA_S + ca];
                af[mi][1] = As[(mR + 8) * LDA_S + ca];
                af[mi][2] = As[mR * LDA_S + ca + 4];
                af[mi][3] = As[(mR + 8) * LDA_S + ca + 4];
            }
#pragma unroll
            for (int ni = 0; ni < 4; ni++) {
                int nB = wc * 32 + ni * 8 + (ln >> 2);
                int kb = kk + (ln & 3);
                bf[ni][0] = Bs[kb * LDB_S + nB];
                bf[ni][1] = Bs[(kb + 4) * LDB_S + nB];
            }
#pragma unroll
            for (int mi = 0; mi < MF; mi++)
#pragma unroll
                for (int ni = 0; ni < 4; ni++)
                    mma_tf32(acc[mi][ni][0], acc[mi][ni][1], acc[mi][ni][2], acc[mi][ni][3],
                             af[mi][0], af[mi][1], af[mi][2], af[mi][3],
                             bf[ni][0], bf[ni][1]);
        }
        __syncthreads();
    }

    // ---- epilogue ----
#pragma unroll
    for (int mi = 0; mi < MF; mi++) {
        int r0 = i0 + wr * (BM / 2) + mi * 16 + (ln >> 2);
        int r1 = r0 + 8;
        float bv0 = bias ? bias[r0] : 0.f;
        float bv1 = bias ? bias[r1] : 0.f;
#pragma unroll
        for (int ni = 0; ni < 4; ni++) {
            int c0 = j0 + wc * 32 + ni * 8 + 2 * (ln & 3);
            float v00 = acc[mi][ni][0] + bv0;
            float v01 = acc[mi][ni][1] + bv0;
            float v10 = acc[mi][ni][2] + bv1;
            float v11 = acc[mi][ni][3] + bv1;
            if (res) {
                float2 r0v = *(const float2*)&res[(size_t)r0 * ldc + c0];
                float2 r1v = *(const float2*)&res[(size_t)r1 * ldc + c0];
                v00 += r0v.x; v01 += r0v.y;
                v10 += r1v.x; v11 += r1v.y;
            }
            *(float2*)&Cm[(size_t)r0 * ldc + c0] = make_float2(v00, v01);
            *(float2*)&Cm[(size_t)r1 * ldc + c0] = make_float2(v10, v11);
        }
    }
}

// ---------------- row softmax ----------------
__global__ void softmax_kernel(float* __restrict__ S) {
    float* p = S + (size_t)blockIdx.x * NN;
    int t = threadIdx.x;
    const float scale = 0.125f;

    float v0 = p[t] * scale;
    float v1 = p[t + 256] * scale;
    float v2 = p[t + 512] * scale;
    float v3 = p[t + 768] * scale;

    __shared__ float red[32];
    float m = fmaxf(fmaxf(v0, v1), fmaxf(v2, v3));
    for (int o = 16; o; o >>= 1) m = fmaxf(m, __shfl_xor_sync(0xffffffffu, m, o));
    if ((t & 31) == 0) red[t >> 5] = m;
    __syncthreads();
    if (t < 32) {
        float x = (t < 8) ? red[t] : -1e30f;
        for (int o = 4; o; o >>= 1) x = fmaxf(x, __shfl_xor_sync(0xffffffffu, x, o));
        if (t == 0) red[0] = x;
    }
    __syncthreads();
    m = red[0];
    __syncthreads();

    v0 = __expf(v0 - m); v1 = __expf(v1 - m);
    v2 = __expf(v2 - m); v3 = __expf(v3 - m);
    float s = v0 + v1 + v2 + v3;
    for (int o = 16; o; o >>= 1) s += __shfl_xor_sync(0xffffffffu, s, o);
    if ((t & 31) == 0) red[t >> 5] = s;
    __syncthreads();
    if (t < 32) {
        float x = (t < 8) ? red[t] : 0.f;
        for (int o = 4; o; o >>= 1) x += __shfl_xor_sync(0xffffffffu, x, o);
        if (t == 0) red[0] = x;
    }
    __syncthreads();
    float inv = 1.0f / red[0];

    p[t]       = v0 * inv;
    p[t + 256] = v1 * inv;
    p[t + 512] = v2 * inv;
    p[t + 768] = v3 * inv;
}

// ---------------- launch ----------------
extern "C" void kernel_launch(void* const* d_in, const int* in_sizes, int n_in,
                              void* d_out, int out_size) {
    (void)in_sizes; (void)n_in; (void)out_size;
    const float* x  = (const float*)d_in[0];
    const float* nw = (const float*)d_in[1];
    const float* nb = (const float*)d_in[2];
    const float* qw = (const float*)d_in[3];
    const float* qb = (const float*)d_in[4];
    const float* pw = (const float*)d_in[5];
    const float* pb = (const float*)d_in[6];
    float* out = (float*)d_out;

    float *xn, *qkv, *sc, *ao;
    cudaGetSymbolAddress((void**)&xn,  g_xn);
    cudaGetSymbolAddress((void**)&qkv, g_qkv);
    cudaGetSymbolAddress((void**)&sc,  g_scores);
    cudaGetSymbolAddress((void**)&ao,  g_ao);

    const long long bCN  = (long long)CC * NN;
    const long long b3CN = 3LL * CC * NN;
    const long long hN   = (long long)HD * NN;
    const long long nnsq = (long long)NN * NN;

    // 1) GroupNorm
    groupnorm_kernel<<<BB * NGROUPS, 256>>>(x, nw, nb, xn);

    // 2) QKV: qkv[b] = qkv_w [1536,512] * xn[b] [512,1024] + qkv_b
    mma_gemm<128, false, false><<<dim3(12, 8, BB), 256>>>(
        qw, xn, qkv, CC, CC, NN, NN,
        0, 0, bCN, 0, b3CN, 0, 1, qb, nullptr, 0, 0);

    // 3) Scores: per (b,h), S = q^T [1024,64] * k [64,1024]
    mma_gemm<128, true, false><<<dim3(8, 8, BB * NHEADS), 256>>>(
        qkv, qkv + (size_t)CC * NN, sc, HD, NN, NN, NN,
        b3CN, hN, b3CN, hN, (long long)NHEADS * nnsq, nnsq, NHEADS,
        nullptr, nullptr, 0, 0);

    // 4) Softmax
    softmax_kernel<<<BB * NHEADS * NN, 256>>>(sc);

    // 5) AV: per (b,h), out[c,n] = v [64,1024] * P^T
    mma_gemm<64, false, true><<<dim3(1, 8, BB * NHEADS), 256>>>(
        qkv + 2 * (size_t)CC * NN, sc, ao, NN, NN, NN, NN,
        b3CN, hN, (long long)NHEADS * nnsq, nnsq, bCN, hN, NHEADS,
        nullptr, nullptr, 0, 0);

    // 6) Proj + bias + residual
    mma_gemm<128, false, false><<<dim3(4, 8, BB), 256>>>(
        pw, ao, out, CC, CC, NN, NN,
        0, 0, bCN, 0, bCN, 0, 1, pb, x, bCN, 0);
}

// round 4
// speedup vs baseline: 3.5655x; 1.7007x over previous
#include <cuda_runtime.h>
#include <cuda_bf16.h>
#include <cstddef>
#include <math_constants.h>

#define BB 8
#define CC 512
#define NHEADS 8
#define HD 64
#define NN 1024
#define NGROUPS 32
#define GSIZE ((CC / NGROUPS) * NN)   // 16384
#define EPSV 1e-5f

// ---------------- scratch ----------------
__device__ float g_xn[BB * CC * NN];       // 16 MB
__device__ float g_qkv[BB * 3 * CC * NN];  // 48 MB
__device__ float g_ao[BB * CC * NN];       // 16 MB

// ---------------- GroupNorm ----------------
__global__ void groupnorm_kernel(const float* __restrict__ x,
                                 const float* __restrict__ w,
                                 const float* __restrict__ bch,
                                 float* __restrict__ xn) {
    int bg = blockIdx.x;
    const float* xp = x + (size_t)bg * GSIZE;
    float* op = xn + (size_t)bg * GSIZE;
    int t = threadIdx.x;

    float s = 0.f, s2 = 0.f;
    for (int i = t; i < GSIZE; i += blockDim.x) {
        float v = xp[i];
        s += v; s2 += v * v;
    }
    __shared__ float rs[32], rs2[32];
    for (int o = 16; o; o >>= 1) {
        s  += __shfl_xor_sync(0xffffffffu, s,  o);
        s2 += __shfl_xor_sync(0xffffffffu, s2, o);
    }
    if ((t & 31) == 0) { rs[t >> 5] = s; rs2[t >> 5] = s2; }
    __syncthreads();
    if (t < 32) {
        int nw = blockDim.x >> 5;
        float a  = (t < nw) ? rs[t]  : 0.f;
        float a2 = (t < nw) ? rs2[t] : 0.f;
        for (int o = 16; o; o >>= 1) {
            a  += __shfl_xor_sync(0xffffffffu, a,  o);
            a2 += __shfl_xor_sync(0xffffffffu, a2, o);
        }
        if (t == 0) {
            float mean = a / (float)GSIZE;
            float var  = a2 / (float)GSIZE - mean * mean;
            rs[0]  = mean;
            rs2[0] = rsqrtf(var + EPSV);
        }
    }
    __syncthreads();
    float mean = rs[0], rstd = rs2[0];
    int c0 = (bg % NGROUPS) * (CC / NGROUPS);
    for (int i = t; i < GSIZE; i += blockDim.x) {
        int c = c0 + i / NN;
        op[i] = (xp[i] - mean) * rstd * w[c] + bch[c];
    }
}

// ---------------- tf32 helpers ----------------
__device__ __forceinline__ unsigned f2tf32(float x) {
    unsigned r;
    asm("cvt.rna.tf32.f32 %0, %1;" : "=r"(r) : "f"(x));
    return r;
}

__device__ __forceinline__ void mma_tf32(float& c0, float& c1, float& c2, float& c3,
                                         unsigned a0, unsigned a1, unsigned a2, unsigned a3,
                                         unsigned b0, unsigned b1) {
    asm volatile(
        "mma.sync.aligned.m16n8k8.row.col.f32.tf32.tf32.f32 "
        "{%0,%1,%2,%3}, {%4,%5,%6,%7}, {%8,%9}, {%0,%1,%2,%3};\n"
        : "+f"(c0), "+f"(c1), "+f"(c2), "+f"(c3)
        : "r"(a0), "r"(a1), "r"(a2), "r"(a3), "r"(b0), "r"(b1));
}

// ---------------- tf32 tensor-core batched GEMM (QKV / proj) ----------------
#define BN 128
#define BK 32
#define LDA_S 36
#define LDB_S 132

template <int BM, bool TA, bool TB>
__global__ __launch_bounds__(256)
void mma_gemm(const float* __restrict__ A,
              const float* __restrict__ Bm,
              float* __restrict__ Cm,
              int K, int lda, int ldb, int ldc,
              long long sAo, long long sAi,
              long long sBo, long long sBi,
              long long sCo, long long sCi,
              int hdiv,
              const float* __restrict__ bias,
              const float* __restrict__ res,
              long long sRo, long long sRi) {
    int z = blockIdx.z;
    int zo = z / hdiv, zi = z % hdiv;
    A  += zo * sAo + zi * sAi;
    Bm += zo * sBo + zi * sBi;
    Cm += zo * sCo + zi * sCi;
    if (res) res += zo * sRo + zi * sRi;

    __shared__ unsigned As[BM * LDA_S];
    __shared__ unsigned Bs[BK * LDB_S];

    const int t  = threadIdx.x;
    const int w  = t >> 5, ln = t & 31;
    const int wr = w >> 2, wc = w & 3;
    const int i0 = blockIdx.x * BM, j0 = blockIdx.y * BN;
    const int MF = BM / 32;

    float acc[MF][4][4];
#pragma unroll
    for (int a = 0; a < MF; a++)
#pragma unroll
        for (int b = 0; b < 4; b++)
#pragma unroll
            for (int c = 0; c < 4; c++) acc[a][b][c] = 0.f;

    for (int k0 = 0; k0 < K; k0 += BK) {
        if (TA) {
#pragma unroll
            for (int r = 0; r < BM * BK / 256; r++) {
                int idx = t + 256 * r;
                int i = idx % BM, k = idx / BM;
                As[i * LDA_S + k] = f2tf32(A[(size_t)(k0 + k) * lda + (i0 + i)]);
            }
        } else {
#pragma unroll
            for (int r = 0; r < BM * BK / 1024; r++) {
                int idx = t + 256 * r;
                int row = idx >> 3, kq = idx & 7;
                float4 v = *(const float4*)&A[(size_t)(i0 + row) * lda + k0 + kq * 4];
                uint4 u;
                u.x = f2tf32(v.x); u.y = f2tf32(v.y);
                u.z = f2tf32(v.z); u.w = f2tf32(v.w);
                *(uint4*)&As[row * LDA_S + kq * 4] = u;
            }
        }
        if (TB) {
#pragma unroll
            for (int r = 0; r < BK * BN / 256; r++) {
                int idx = t + 256 * r;
                int k = idx & 31, j = idx >> 5;
                Bs[k * LDB_S + j] = f2tf32(Bm[(size_t)(j0 + j) * ldb + (k0 + k)]);
            }
        } else {
#pragma unroll
            for (int r = 0; r < BK * BN / 1024; r++) {
                int idx = t + 256 * r;
                int k = idx >> 5, jq = idx & 31;
                float4 v = *(const float4*)&Bm[(size_t)(k0 + k) * ldb + j0 + jq * 4];
                uint4 u;
                u.x = f2tf32(v.x); u.y = f2tf32(v.y);
                u.z = f2tf32(v.z); u.w = f2tf32(v.w);
                *(uint4*)&Bs[k * LDB_S + jq * 4] = u;
            }
        }
        __syncthreads();

#pragma unroll
        for (int ks = 0; ks < 4; ks++) {
            int kk = ks * 8;
            unsigned af[MF][4];
            unsigned bf[4][2];
#pragma unroll
            for (int mi = 0; mi < MF; mi++) {
                int mR = wr * (BM / 2) + mi * 16 + (ln >> 2);
                int ca = kk + (ln & 3);
                af[mi][0] = As[mR * LDA_S + ca];
                af[mi][1] = As[(mR + 8) * LDA_S + ca];
                af[mi][2] = As[mR * LDA_S + ca + 4];
                af[mi][3] = As[(mR + 8) * LDA_S + ca + 4];
            }
#pragma unroll
            for (int ni = 0; ni < 4; ni++) {
                int nB = wc * 32 + ni * 8 + (ln >> 2);
                int kb = kk + (ln & 3);
                bf[ni][0] = Bs[kb * LDB_S + nB];
                bf[ni][1] = Bs[(kb + 4) * LDB_S + nB];
            }
#pragma unroll
            for (int mi = 0; mi < MF; mi++)
#pragma unroll
                for (int ni = 0; ni < 4; ni++)
                    mma_tf32(acc[mi][ni][0], acc[mi][ni][1], acc[mi][ni][2], acc[mi][ni][3],
                             af[mi][0], af[mi][1], af[mi][2], af[mi][3],
                             bf[ni][0], bf[ni][1]);
        }
        __syncthreads();
    }

#pragma unroll
    for (int mi = 0; mi < MF; mi++) {
        int r0 = i0 + wr * (BM / 2) + mi * 16 + (ln >> 2);
        int r1 = r0 + 8;
        float bv0 = bias ? bias[r0] : 0.f;
        float bv1 = bias ? bias[r1] : 0.f;
#pragma unroll
        for (int ni = 0; ni < 4; ni++) {
            int c0 = j0 + wc * 32 + ni * 8 + 2 * (ln & 3);
            float v00 = acc[mi][ni][0] + bv0;
            float v01 = acc[mi][ni][1] + bv0;
            float v10 = acc[mi][ni][2] + bv1;
            float v11 = acc[mi][ni][3] + bv1;
            if (res) {
                float2 r0v = *(const float2*)&res[(size_t)r0 * ldc + c0];
                float2 r1v = *(const float2*)&res[(size_t)r1 * ldc + c0];
                v00 += r0v.x; v01 += r0v.y;
                v10 += r1v.x; v11 += r1v.y;
            }
            *(float2*)&Cm[(size_t)r0 * ldc + c0] = make_float2(v00, v01);
            *(float2*)&Cm[(size_t)r1 * ldc + c0] = make_float2(v10, v11);
        }
    }
}

// ---------------- fused flash attention ----------------
// grid: (NN/128, BB*NHEADS); 256 threads = 8 warps, each warp owns 16 query rows.
#define QT 128
#define MT 64
#define QS_LD 68   // [128 q][64 c] row stride 64+4  (FIX: was 36 -> row aliasing)
#define KS_LD 72   // [64 c][64 m]  row stride 64+8
#define VS_LD 68   // [64 c][64 m]  row stride 64+4
#define SMEM_U32 (QT * QS_LD + HD * KS_LD + HD * VS_LD)   // 8704+4608+4352 = 17664

__global__ __launch_bounds__(256)
void flash_attn(const float* __restrict__ qkv, float* __restrict__ ao) {
    extern __shared__ unsigned sm[];
    unsigned* Qs = sm;
    unsigned* Ks = sm + QT * QS_LD;
    unsigned* Vs = Ks + HD * KS_LD;

    const int t = threadIdx.x;
    const int w = t >> 5, ln = t & 31;
    const int r = ln >> 2, j = ln & 3;
    const int bh = blockIdx.y;
    const int b = bh >> 3, h = bh & 7;
    const int q0 = blockIdx.x * QT;
    const int qrow = w * 16 + r;

    const float* Qp = qkv + (size_t)b * 3 * CC * NN + (size_t)h * HD * NN;
    const float* Kp = Qp + (size_t)CC * NN;
    const float* Vp = Qp + 2 * (size_t)CC * NN;

    // load Q tile -> Qs[q][c], tf32
    for (int idx = t; idx < QT * HD; idx += 256) {
        int q = idx & (QT - 1), c = idx >> 7;
        Qs[q * QS_LD + c] = f2tf32(Qp[(size_t)c * NN + q0 + q]);
    }

    float o[8][4];
#pragma unroll
    for (int a = 0; a < 8; a++)
#pragma unroll
        for (int bq = 0; bq < 4; bq++) o[a][bq] = 0.f;
    float m0v = -CUDART_INF_F, m1v = -CUDART_INF_F;
    float l0 = 0.f, l1 = 0.f;

    const int src0 = (ln & ~3) | (j >> 1);
    const int src1 = src0 + 2;

    for (int it = 0; it < NN / MT; it++) {
        int mo = it * MT;
        __syncthreads();
        for (int idx = t; idx < HD * MT / 4; idx += 256) {
            int c = idx >> 4, mq = (idx & 15) * 4;
            float4 kv = *(const float4*)&Kp[(size_t)c * NN + mo + mq];
            uint4 uk;
            uk.x = f2tf32(kv.x); uk.y = f2tf32(kv.y);
            uk.z = f2tf32(kv.z); uk.w = f2tf32(kv.w);
            *(uint4*)&Ks[c * KS_LD + mq] = uk;
            float4 vv = *(const float4*)&Vp[(size_t)c * NN + mo + mq];
            uint4 uv;
            uv.x = f2tf32(vv.x); uv.y = f2tf32(vv.y);
            uv.z = f2tf32(vv.z); uv.w = f2tf32(vv.w);
            *(uint4*)&Vs[c * VS_LD + mq] = uv;
        }
        __syncthreads();

        // ---- S = Q^T K ----
        float s[8][4];
#pragma unroll
        for (int a = 0; a < 8; a++)
#pragma unroll
            for (int bq = 0; bq < 4; bq++) s[a][bq] = 0.f;

#pragma unroll
        for (int kf = 0; kf < 8; kf++) {
            int ca = kf * 8 + j;
            unsigned a0 = Qs[qrow * QS_LD + ca];
            unsigned a1 = Qs[(qrow + 8) * QS_LD + ca];
            unsigned a2 = Qs[qrow * QS_LD + ca + 4];
            unsigned a3 = Qs[(qrow + 8) * QS_LD + ca + 4];
#pragma unroll
            for (int ni = 0; ni < 8; ni++) {
                unsigned b0 = Ks[ca * KS_LD + ni * 8 + r];
                unsigned b1 = Ks[(ca + 4) * KS_LD + ni * 8 + r];
                mma_tf32(s[ni][0], s[ni][1], s[ni][2], s[ni][3], a0, a1, a2, a3, b0, b1);
            }
        }

        // ---- online softmax ----
        float tm0 = -CUDART_INF_F, tm1 = -CUDART_INF_F;
#pragma unroll
        for (int ni = 0; ni < 8; ni++) {
            s[ni][0] *= 0.125f; s[ni][1] *= 0.125f;
            s[ni][2] *= 0.125f; s[ni][3] *= 0.125f;
            tm0 = fmaxf(tm0, fmaxf(s[ni][0], s[ni][1]));
            tm1 = fmaxf(tm1, fmaxf(s[ni][2], s[ni][3]));
        }
        tm0 = fmaxf(tm0, __shfl_xor_sync(0xffffffffu, tm0, 1));
        tm0 = fmaxf(tm0, __shfl_xor_sync(0xffffffffu, tm0, 2));
        tm1 = fmaxf(tm1, __shfl_xor_sync(0xffffffffu, tm1, 1));
        tm1 = fmaxf(tm1, __shfl_xor_sync(0xffffffffu, tm1, 2));

        float mn0 = fmaxf(m0v, tm0), mn1 = fmaxf(m1v, tm1);
        float al0 = __expf(m0v - mn0), al1 = __expf(m1v - mn1);
        m0v = mn0; m1v = mn1;

        float rs0 = 0.f, rs1 = 0.f;
#pragma unroll
        for (int ni = 0; ni < 8; ni++) {
            s[ni][0] = __expf(s[ni][0] - mn0);
            s[ni][1] = __expf(s[ni][1] - mn0);
            s[ni][2] = __expf(s[ni][2] - mn1);
            s[ni][3] = __expf(s[ni][3] - mn1);
            rs0 += s[ni][0] + s[ni][1];
            rs1 += s[ni][2] + s[ni][3];
        }
        rs0 += __shfl_xor_sync(0xffffffffu, rs0, 1);
        rs0 += __shfl_xor_sync(0xffffffffu, rs0, 2);
        rs1 += __shfl_xor_sync(0xffffffffu, rs1, 1);
        rs1 += __shfl_xor_sync(0xffffffffu, rs1, 2);
        l0 = l0 * al0 + rs0;
        l1 = l1 * al1 + rs1;

#pragma unroll
        for (int no = 0; no < 8; no++) {
            o[no][0] *= al0; o[no][1] *= al0;
            o[no][2] *= al1; o[no][3] *= al1;
        }

        // ---- O += P * V^T : C-frag -> A-frag via quad shuffles ----
#pragma unroll
        for (int km = 0; km < 8; km++) {
            float q00 = __shfl_sync(0xffffffffu, s[km][0], src0);
            float q01 = __shfl_sync(0xffffffffu, s[km][1], src0);
            float q10 = __shfl_sync(0xffffffffu, s[km][0], src1);
            float q11 = __shfl_sync(0xffffffffu, s[km][1], src1);
            float q20 = __shfl_sync(0xffffffffu, s[km][2], src0);
            float q21 = __shfl_sync(0xffffffffu, s[km][3], src0);
            float q30 = __shfl_sync(0xffffffffu, s[km][2], src1);
            float q31 = __shfl_sync(0xffffffffu, s[km][3], src1);
            unsigned pa0 = f2tf32((j & 1) ? q01 : q00);
            unsigned pa2 = f2tf32((j & 1) ? q11 : q10);
            unsigned pa1 = f2tf32((j & 1) ? q21 : q20);
            unsigned pa3 = f2tf32((j & 1) ? q31 : q30);
#pragma unroll
            for (int no = 0; no < 8; no++) {
                unsigned b0 = Vs[(no * 8 + r) * VS_LD + km * 8 + j];
                unsigned b1 = Vs[(no * 8 + r) * VS_LD + km * 8 + j + 4];
                mma_tf32(o[no][0], o[no][1], o[no][2], o[no][3], pa0, pa1, pa2, pa3, b0, b1);
            }
        }
    }

    // ---- epilogue ----
    float inv0 = 1.f / l0, inv1 = 1.f / l1;
    float* aop = ao + (size_t)b * CC * NN + (size_t)h * HD * NN;
#pragma unroll
    for (int no = 0; no < 8; no++) {
        int hd0 = no * 8 + 2 * j;
        aop[(size_t)hd0 * NN + q0 + qrow]           = o[no][0] * inv0;
        aop[(size_t)(hd0 + 1) * NN + q0 + qrow]     = o[no][1] * inv0;
        aop[(size_t)hd0 * NN + q0 + qrow + 8]       = o[no][2] * inv1;
        aop[(size_t)(hd0 + 1) * NN + q0 + qrow + 8] = o[no][3] * inv1;
    }
}

// ---------------- launch ----------------
extern "C" void kernel_launch(void* const* d_in, const int* in_sizes, int n_in,
                              void* d_out, int out_size) {
    (void)in_sizes; (void)n_in; (void)out_size;
    const float* x  = (const float*)d_in[0];
    const float* nw = (const float*)d_in[1];
    const float* nb = (const float*)d_in[2];
    const float* qw = (const float*)d_in[3];
    const float* qb = (const float*)d_in[4];
    const float* pw = (const float*)d_in[5];
    const float* pb = (const float*)d_in[6];
    float* out = (float*)d_out;

    float *xn, *qkv, *ao;
    cudaGetSymbolAddress((void**)&xn,  g_xn);
    cudaGetSymbolAddress((void**)&qkv, g_qkv);
    cudaGetSymbolAddress((void**)&ao,  g_ao);

    const long long bCN  = (long long)CC * NN;
    const long long b3CN = 3LL * CC * NN;

    cudaFuncSetAttribute(flash_attn, cudaFuncAttributeMaxDynamicSharedMemorySize,
                         SMEM_U32 * 4);

    // 1) GroupNorm
    groupnorm_kernel<<<BB * NGROUPS, 256>>>(x, nw, nb, xn);

    // 2) QKV: qkv[b] = qkv_w [1536,512] * xn[b] [512,1024] + qkv_b
    mma_gemm<128, false, false><<<dim3(12, 8, BB), 256>>>(
        qw, xn, qkv, CC, CC, NN, NN,
        0, 0, bCN, 0, b3CN, 0, 1, qb, nullptr, 0, 0);

    // 3) Fused attention: scores + softmax + AV
    flash_attn<<<dim3(NN / QT, BB * NHEADS), 256, SMEM_U32 * 4>>>(qkv, ao);

    // 4) Proj + bias + residual
    mma_gemm<128, false, false><<<dim3(4, 8, BB), 256>>>(
        pw, ao, out, CC, CC, NN, NN,
        0, 0, bCN, 0, bCN, 0, 1, pb, x, bCN, 0);
}